// round 5
// baseline (speedup 1.0000x reference)
#include <cuda_runtime.h>
#include <cstdint>

#define K_DIM   128
#define O_DIM   128
#define CHUNK   64            // rows of x per iteration
#define THREADS 256           // 8 warps: 4 o-groups x 2 m-groups

// x is fed to the tf32 MMA as raw fp32 bits (HW truncates to tf32).
// Mean relative shrink of truncation = 2^-11 * ln2 = 3.38e-4; compensate on W.
#define W_SCALE 1.000338f

__device__ __forceinline__ uint32_t cvt_tf32(float f) {
    uint32_t r;
    asm("cvt.rna.tf32.f32 %0, %1;" : "=r"(r) : "f"(f));
    return r;
}

// k-permutation: logical k (t, t+4) of MMA step s maps to physical columns
//   col0 = 16*(s>>1) + 4*t + 2*(s&1),  col1 = col0 + 1
// Applied identically to A (x) and B (W), so the GEMM result is unchanged,
// and each thread's A fragment for TWO k-steps is one contiguous float4.

__global__ void __launch_bounds__(THREADS, 1)
qlinear_tf32_reg(const float* __restrict__ x,
                 const float* __restrict__ W,
                 float* __restrict__ out,
                 int nrows, int nchunks)
{
    const int tid  = threadIdx.x;
    const int lane = tid & 31, wid = tid >> 5;
    const int q = lane >> 2;        // groupID (0..7)
    const int t = lane & 3;         // threadID in group (0..3)
    const int wo = wid & 3;         // o-group: cols [wo*32, wo*32+32)
    const int wm = wid >> 2;        // m-group: rows [wm*32, wm*32+32) of chunk

    // ---- B fragments: register-resident, permuted-k, rna + compensation ----
    uint32_t Bf[16][4][2];
    #pragma unroll
    for (int s = 0; s < 16; s++) {
        const int col = 16 * (s >> 1) + 4 * t + 2 * (s & 1);
        #pragma unroll
        for (int tt = 0; tt < 4; tt++) {
            const int n = wo * 32 + tt * 8 + q;
            float2 w = *reinterpret_cast<const float2*>(W + n * K_DIM + col);
            Bf[s][tt][0] = cvt_tf32(w.x * W_SCALE);
            Bf[s][tt][1] = cvt_tf32(w.y * W_SCALE);
        }
    }

    // ---- main loop: pure LDG.128 -> MMA, no smem, no barriers ----
    for (int c = blockIdx.x; c < nchunks; c += gridDim.x) {
        const int rbase = c * CHUNK + wm * 32 + q;

        // 4 row-groups: q, q+8 (mt=0) and q+16, q+24 (mt=1); clamp for safety
        const float* xp0; const float* xp1; const float* xp2; const float* xp3;
        {
            int r0 = rbase,      r1 = rbase + 8,  r2 = rbase + 16, r3 = rbase + 24;
            if (r0 >= nrows) r0 = nrows - 1;
            if (r1 >= nrows) r1 = nrows - 1;
            if (r2 >= nrows) r2 = nrows - 1;
            if (r3 >= nrows) r3 = nrows - 1;
            const float* xt = x + 4 * t;
            xp0 = xt + (size_t)r0 * K_DIM;
            xp1 = xt + (size_t)r1 * K_DIM;
            xp2 = xt + (size_t)r2 * K_DIM;
            xp3 = xt + (size_t)r3 * K_DIM;
        }

        float acc[2][4][4];
        #pragma unroll
        for (int mt = 0; mt < 2; mt++)
            #pragma unroll
            for (int tt = 0; tt < 4; tt++)
                #pragma unroll
                for (int e = 0; e < 4; e++) acc[mt][tt][e] = 0.0f;

        #pragma unroll
        for (int sp = 0; sp < 8; sp++) {        // step-pair: covers k-steps 2sp, 2sp+1
            float4 v0 = *reinterpret_cast<const float4*>(xp0 + sp * 16);
            float4 v1 = *reinterpret_cast<const float4*>(xp1 + sp * 16);
            float4 v2 = *reinterpret_cast<const float4*>(xp2 + sp * 16);
            float4 v3 = *reinterpret_cast<const float4*>(xp3 + sp * 16);

            #pragma unroll
            for (int st = 0; st < 2; st++) {
                const int s = 2 * sp + st;
                uint32_t a[2][4];
                a[0][0] = __float_as_uint(st ? v0.z : v0.x);
                a[0][2] = __float_as_uint(st ? v0.w : v0.y);
                a[0][1] = __float_as_uint(st ? v1.z : v1.x);
                a[0][3] = __float_as_uint(st ? v1.w : v1.y);
                a[1][0] = __float_as_uint(st ? v2.z : v2.x);
                a[1][2] = __float_as_uint(st ? v2.w : v2.y);
                a[1][1] = __float_as_uint(st ? v3.z : v3.x);
                a[1][3] = __float_as_uint(st ? v3.w : v3.y);

                #pragma unroll
                for (int mt = 0; mt < 2; mt++)
                    #pragma unroll
                    for (int tt = 0; tt < 4; tt++) {
                        asm volatile(
                            "mma.sync.aligned.m16n8k8.row.col.f32.tf32.tf32.f32 "
                            "{%0,%1,%2,%3}, {%4,%5,%6,%7}, {%8,%9}, {%0,%1,%2,%3};"
                            : "+f"(acc[mt][tt][0]), "+f"(acc[mt][tt][1]),
                              "+f"(acc[mt][tt][2]), "+f"(acc[mt][tt][3])
                            : "r"(a[mt][0]), "r"(a[mt][1]), "r"(a[mt][2]), "r"(a[mt][3]),
                              "r"(Bf[s][tt][0]), "r"(Bf[s][tt][1]));
                    }
            }
        }

        // ---- epilogue: 8B sector-aligned float2 stores ----
        #pragma unroll
        for (int mt = 0; mt < 2; mt++) {
            const int r1 = c * CHUNK + wm * 32 + mt * 16 + q;
            const int r2 = r1 + 8;
            #pragma unroll
            for (int tt = 0; tt < 4; tt++) {
                const int col = wo * 32 + tt * 8 + 2 * t;
                if (r1 < nrows)
                    *reinterpret_cast<float2*>(out + (size_t)r1 * O_DIM + col) =
                        make_float2(acc[mt][tt][0], acc[mt][tt][1]);
                if (r2 < nrows)
                    *reinterpret_cast<float2*>(out + (size_t)r2 * O_DIM + col) =
                        make_float2(acc[mt][tt][2], acc[mt][tt][3]);
            }
        }
    }
}

extern "C" void kernel_launch(void* const* d_in, const int* in_sizes, int n_in,
                              void* d_out, int out_size)
{
    const float* x = (const float*)d_in[0];
    const float* W = (const float*)d_in[1];
    float* out = (float*)d_out;

    const int nrows   = in_sizes[0] / K_DIM;
    const int nchunks = (nrows + CHUNK - 1) / CHUNK;

    int sms = 148;
    cudaDeviceGetAttribute(&sms, cudaDevAttrMultiProcessorCount, 0);
    int grid = sms;
    if (grid > nchunks) grid = nchunks;
    if (grid < 1) grid = 1;

    qlinear_tf32_reg<<<grid, THREADS>>>(x, W, out, nrows, nchunks);
}

// round 6
// speedup vs baseline: 1.8410x; 1.8410x over previous
#include <cuda_runtime.h>
#include <cstdint>

#define K_DIM      128
#define O_DIM      128
#define CHUNK      64          // rows of x per pipeline stage
#define THREADS    256         // 8 warps: 4 o-groups x 2 m-groups
#define LDS_STRIDE 136         // conflict-free LDS.64 phases: banks 8q+2t distinct
#define NBUF       4           // ring depth (3 chunks in flight)
#define BUF_FLOATS (CHUNK * LDS_STRIDE)
#define SMEM_BYTES (NBUF * BUF_FLOATS * 4)   // 139264 B

// x feeds the tf32 MMA as raw fp32 bits (HW truncates to tf32).
// Mean relative shrink of truncation = 2^-11 * ln2 = 3.38e-4; compensate on W.
#define W_SCALE 1.000338f

__device__ __forceinline__ uint32_t cvt_tf32(float f) {
    uint32_t r;
    asm("cvt.rna.tf32.f32 %0, %1;" : "=r"(r) : "f"(f));
    return r;
}
__device__ __forceinline__ void cp_async16(uint32_t smem_addr, const void* gptr) {
    asm volatile("cp.async.cg.shared.global [%0], [%1], 16;" :: "r"(smem_addr), "l"(gptr));
}
__device__ __forceinline__ void cp_commit() {
    asm volatile("cp.async.commit_group;");
}

// k-permutation: MMA step s, thread t covers logical k {t, t+4}, mapped to
// physical columns {8s+2t, 8s+2t+1}. Applied to BOTH A (x, via smem col index)
// and B (W, via gmem col index) -> GEMM result unchanged; A frag = one LDS.64.

__global__ void __launch_bounds__(THREADS, 1)
qlinear_tf32_kernel(const float* __restrict__ x,
                    const float* __restrict__ W,
                    float* __restrict__ out,
                    int nrows, int nchunks)
{
    extern __shared__ float smem[];
    const int tid = threadIdx.x;
    const uint32_t smem_a = (uint32_t)__cvta_generic_to_shared(smem);

    const int lane = tid & 31, wid = tid >> 5;
    const int q = lane >> 2;        // groupID (0..7)
    const int t = lane & 3;         // threadID in group (0..3)
    const int wo = wid & 3;         // o-group: cols [wo*32, wo*32+32)
    const int wm = wid >> 2;        // m-group: rows [wm*32, wm*32+32) of chunk

    auto stage = [&](int chunk, int buf) {
        if (chunk < nchunks) {
            int row0 = chunk * CHUNK;
            uint32_t base = smem_a + (uint32_t)(buf * BUF_FLOATS) * 4;
            #pragma unroll
            for (int j = 0; j < 8; j++) {
                int flat = tid + j * THREADS;       // 0..2047 float4s
                int r  = flat >> 5;                 // 0..63
                int c4 = flat & 31;
                int gr = row0 + r;
                if (gr >= nrows) gr = nrows - 1;    // clamp: never OOB, data unused
                cp_async16(base + (uint32_t)(r * LDS_STRIDE + c4 * 4) * 4,
                           x + (size_t)gr * K_DIM + c4 * 4);
            }
        }
    };

    const int c0 = blockIdx.x;
    const int g  = gridDim.x;

    // start the ring immediately: 3 chunks in flight
    stage(c0 + 0 * g, 0); cp_commit();
    stage(c0 + 1 * g, 1); cp_commit();
    stage(c0 + 2 * g, 2); cp_commit();

    // ---- B fragments straight from gmem (L2-served; one-time), permuted k ----
    uint32_t Bf[16][4][2];
    #pragma unroll
    for (int s = 0; s < 16; s++) {
        const int col = 8 * s + 2 * t;
        #pragma unroll
        for (int tt = 0; tt < 4; tt++) {
            const int n = wo * 32 + tt * 8 + q;
            float2 w = *reinterpret_cast<const float2*>(W + n * K_DIM + col);
            Bf[s][tt][0] = cvt_tf32(w.x * W_SCALE);
            Bf[s][tt][1] = cvt_tf32(w.y * W_SCALE);
        }
    }

    // ---- main pipeline ----
    int idx = 0;
    for (int c = c0; c < nchunks; c += g, idx++) {
        const int buf = idx & (NBUF - 1);
        asm volatile("cp.async.wait_group 2;");     // this chunk's buffer arrived
        __syncthreads();                            // visible to all; buf(idx-1) drained

        // restage the buffer consumed LAST iteration: safe post-barrier
        stage(c + 3 * g, (buf + 3) & (NBUF - 1));
        cp_commit();

        // thread's A base: row (wm*32+q), physical col 2t
        const float* xb = smem + buf * BUF_FLOATS + (wm * 32 + q) * LDS_STRIDE + 2 * t;

        float acc[2][4][4];
        #pragma unroll
        for (int mt = 0; mt < 2; mt++)
            #pragma unroll
            for (int tt = 0; tt < 4; tt++)
                #pragma unroll
                for (int e = 0; e < 4; e++) acc[mt][tt][e] = 0.0f;

        // software pipeline: prefetch step s+1 A-frags while MMA-ing step s
        float2 cur[4], nxt[4];
        cur[0] = *reinterpret_cast<const float2*>(xb);                    // q,    mt0
        cur[1] = *reinterpret_cast<const float2*>(xb +  8 * LDS_STRIDE);  // q+8,  mt0
        cur[2] = *reinterpret_cast<const float2*>(xb + 16 * LDS_STRIDE);  // q+16, mt1
        cur[3] = *reinterpret_cast<const float2*>(xb + 24 * LDS_STRIDE);  // q+24, mt1

        #pragma unroll
        for (int s = 0; s < 16; s++) {
            if (s < 15) {
                const float* p = xb + (s + 1) * 8;
                nxt[0] = *reinterpret_cast<const float2*>(p);
                nxt[1] = *reinterpret_cast<const float2*>(p +  8 * LDS_STRIDE);
                nxt[2] = *reinterpret_cast<const float2*>(p + 16 * LDS_STRIDE);
                nxt[3] = *reinterpret_cast<const float2*>(p + 24 * LDS_STRIDE);
            }
            #pragma unroll
            for (int mt = 0; mt < 2; mt++) {
                const uint32_t a0 = __float_as_uint(cur[2*mt    ].x);
                const uint32_t a2 = __float_as_uint(cur[2*mt    ].y);
                const uint32_t a1 = __float_as_uint(cur[2*mt + 1].x);
                const uint32_t a3 = __float_as_uint(cur[2*mt + 1].y);
                #pragma unroll
                for (int tt = 0; tt < 4; tt++) {
                    asm volatile(
                        "mma.sync.aligned.m16n8k8.row.col.f32.tf32.tf32.f32 "
                        "{%0,%1,%2,%3}, {%4,%5,%6,%7}, {%8,%9}, {%0,%1,%2,%3};"
                        : "+f"(acc[mt][tt][0]), "+f"(acc[mt][tt][1]),
                          "+f"(acc[mt][tt][2]), "+f"(acc[mt][tt][3])
                        : "r"(a0), "r"(a1), "r"(a2), "r"(a3),
                          "r"(Bf[s][tt][0]), "r"(Bf[s][tt][1]));
                }
            }
            #pragma unroll
            for (int u = 0; u < 4; u++) cur[u] = nxt[u];
        }

        // ---- epilogue: 8B sector-aligned float2 stores ----
        #pragma unroll
        for (int mt = 0; mt < 2; mt++) {
            const int r1 = c * CHUNK + wm * 32 + mt * 16 + q;
            const int r2 = r1 + 8;
            #pragma unroll
            for (int tt = 0; tt < 4; tt++) {
                const int col = wo * 32 + tt * 8 + 2 * t;
                if (r1 < nrows)
                    *reinterpret_cast<float2*>(out + (size_t)r1 * O_DIM + col) =
                        make_float2(acc[mt][tt][0], acc[mt][tt][1]);
                if (r2 < nrows)
                    *reinterpret_cast<float2*>(out + (size_t)r2 * O_DIM + col) =
                        make_float2(acc[mt][tt][2], acc[mt][tt][3]);
            }
        }
    }
}

extern "C" void kernel_launch(void* const* d_in, const int* in_sizes, int n_in,
                              void* d_out, int out_size)
{
    const float* x = (const float*)d_in[0];
    const float* W = (const float*)d_in[1];
    float* out = (float*)d_out;

    const int nrows   = in_sizes[0] / K_DIM;
    const int nchunks = (nrows + CHUNK - 1) / CHUNK;

    cudaFuncSetAttribute(qlinear_tf32_kernel,
                         cudaFuncAttributeMaxDynamicSharedMemorySize, SMEM_BYTES);

    int sms = 148;
    cudaDeviceGetAttribute(&sms, cudaDevAttrMultiProcessorCount, 0);
    int grid = sms;
    if (grid > nchunks) grid = nchunks;
    if (grid < 1) grid = 1;

    qlinear_tf32_kernel<<<grid, THREADS, SMEM_BYTES>>>(x, W, out, nrows, nchunks);
}